// round 9
// baseline (speedup 1.0000x reference)
#include <cuda_runtime.h>
#include <cstdint>

// Shapes (fixed by the problem)
#define BB    8
#define CC    512
#define NN    1024
#define HH    8
#define DD    64
#define CQKV  1536   // q,k,v output channels stacked

// ---------------------------------------------------------------------------
// Device scratch (static __device__ arrays — allocation-free per harness rules)
// ---------------------------------------------------------------------------
__device__ float g_xq[BB * CC * NN];                 // spikes after pre BN+LIF (0/1 fp32)
__device__ float g_z [BB * CQKV * NN];               // Wqkv @ xq (pre-BN)
__device__ float g_sq[BB * CC * NN];                 // q spikes fp32
__device__ unsigned long long g_kb[BB * CC * 16];    // k spikes bitpacked along n
__device__ unsigned long long g_vb[BB * CC * 16];    // v spikes bitpacked along n
__device__ float g_y [BB * CC * NN];                 // attention output * 0.25 (exact ints*0.25)
__device__ float g_sy[BB * CC * NN];                 // attn LIF spikes fp32

// ---------------------------------------------------------------------------
// K1 / K5: generic (optional BN) + LIF scan over N.  128 rows per block,
// one thread per row, smem tiling (pad 33) for coalesced global traffic.
// ---------------------------------------------------------------------------
__global__ __launch_bounds__(128) void lif_bn_kernel(
    const float* __restrict__ in, const float* __restrict__ bnp,
    float* __restrict__ out, float vth)
{
    __shared__ float tile[128][33];
    const int tid = threadIdx.x;
    const int r0  = blockIdx.x * 128;
    const int row = r0 + tid;

    float inv = 1.0f, mu = 0.0f, be = 0.0f;
    if (bnp) {
        int c = row & (CC - 1);
        float g  = bnp[c];
        float bb = bnp[CC + c];
        float m  = bnp[2 * CC + c];
        float va = bnp[3 * CC + c];
        inv = g * (1.0f / sqrtf(va + 1e-5f));
        mu = m; be = bb;
    }

    const int lr0 = tid >> 5;
    const int col = tid & 31;
    float v = 0.0f;

    for (int t = 0; t < NN / 32; t++) {
        for (int p = 0; p < 32; p++) {
            int lr = lr0 + p * 4;
            tile[lr][col] = in[(size_t)(r0 + lr) * NN + t * 32 + col];
        }
        __syncthreads();
        #pragma unroll
        for (int kk = 0; kk < 32; kk++) {
            float xb = (tile[tid][kk] - mu) * inv + be;
            v = v + (xb - v) * 0.5f;
            bool sp = (v >= vth);
            tile[tid][kk] = sp ? 1.0f : 0.0f;
            v = sp ? 0.0f : v;
        }
        __syncthreads();
        for (int p = 0; p < 32; p++) {
            int lr = lr0 + p * 4;
            out[(size_t)(r0 + lr) * NN + t * 32 + col] = tile[lr][col];
        }
        __syncthreads();
    }
}

// ---------------------------------------------------------------------------
// K3: BN (per-branch) + LIF on the stacked QKV GEMM output.
//   branch 0 (q): spikes -> g_sq as fp32
//   branch 1 (k): spikes -> g_kb bitpacked along n
//   branch 2 (v): spikes -> g_vb bitpacked along n
// Blocks of 128 rows never straddle a batch or a branch (1536 = 12*128, 512 = 4*128).
// ---------------------------------------------------------------------------
__global__ __launch_bounds__(128) void lif_qkv_kernel(
    const float* __restrict__ bnq, const float* __restrict__ bnk,
    const float* __restrict__ bnv)
{
    __shared__ float tile[128][33];
    const int tid = threadIdx.x;
    const int r0  = blockIdx.x * 128;
    const int b   = r0 / CQKV;
    const int o0  = r0 % CQKV;
    const int branch = o0 / CC;
    const int c0  = o0 % CC;

    const float* bnp = (branch == 0) ? bnq : (branch == 1) ? bnk : bnv;
    const int c = c0 + tid;
    float g  = bnp[c];
    float be = bnp[CC + c];
    float mu = bnp[2 * CC + c];
    float va = bnp[3 * CC + c];
    float inv = g * (1.0f / sqrtf(va + 1e-5f));

    const float* inbase = g_z + (size_t)r0 * NN;
    float* outq = g_sq + ((size_t)b * CC + c0) * NN;
    unsigned long long* outb = (branch == 1) ? g_kb : g_vb;
    const size_t brow = ((size_t)b * CC + c) * 16;

    const int lr0 = tid >> 5;
    const int col = tid & 31;
    float v = 0.0f;
    unsigned long long cur = 0ull;

    for (int t = 0; t < NN / 32; t++) {
        for (int p = 0; p < 32; p++) {
            int lr = lr0 + p * 4;
            tile[lr][col] = inbase[(size_t)lr * NN + t * 32 + col];
        }
        __syncthreads();
        const int bitbase = (t & 1) << 5;
        #pragma unroll
        for (int kk = 0; kk < 32; kk++) {
            float xb = (tile[tid][kk] - mu) * inv + be;
            v = v + (xb - v) * 0.5f;
            bool sp = (v >= 1.0f);
            tile[tid][kk] = sp ? 1.0f : 0.0f;
            if (sp) cur |= 1ull << (bitbase + kk);
            v = sp ? 0.0f : v;
        }
        __syncthreads();
        if (branch == 0) {
            for (int p = 0; p < 32; p++) {
                int lr = lr0 + p * 4;
                outq[(size_t)lr * NN + t * 32 + col] = tile[lr][col];
            }
        } else if (t & 1) {
            outb[brow + (t >> 1)] = cur;
            cur = 0ull;
        }
        __syncthreads();
    }
}

// ---------------------------------------------------------------------------
// K2: fused QKV GEMM.  For each batch b: Z[1536,1024] = Wqkv[1536,512] @ xq_b.
// 128x128 tiles, BK=16, 256 threads, 8x8 microtile, fp32 (exact vs spikes).
// ---------------------------------------------------------------------------
__global__ __launch_bounds__(256) void gemm_qkv_kernel(
    const float* __restrict__ wq, const float* __restrict__ wk,
    const float* __restrict__ wv)
{
    __shared__ __align__(16) float As[16][128];
    __shared__ __align__(16) float Bs[16][128];

    const int b  = blockIdx.z;
    const int mt = blockIdx.y;   // 0..11 (q: 0-3, k: 4-7, v: 8-11)
    const int nt = blockIdx.x;   // 0..7
    const float* W = (mt < 4) ? wq : (mt < 8) ? wk : wv;
    const float* A = W + (size_t)(mt & 3) * 128 * CC;
    const float* Bp = g_xq + (size_t)b * (CC * NN) + nt * 128;
    float* Cp = g_z + (size_t)b * (CQKV * NN) + (size_t)mt * 128 * NN + nt * 128;

    const int tid = threadIdx.x;
    const int tx = tid & 15, ty = tid >> 4;

    float acc[8][8];
    #pragma unroll
    for (int i = 0; i < 8; i++)
        #pragma unroll
        for (int j = 0; j < 8; j++) acc[i][j] = 0.0f;

    for (int k0 = 0; k0 < CC; k0 += 16) {
        #pragma unroll
        for (int i = 0; i < 2; i++) {
            int id = tid * 2 + i;
            int row = id >> 2, kq = id & 3;
            float4 v = *(const float4*)(A + (size_t)row * CC + k0 + kq * 4);
            As[kq * 4 + 0][row] = v.x;
            As[kq * 4 + 1][row] = v.y;
            As[kq * 4 + 2][row] = v.z;
            As[kq * 4 + 3][row] = v.w;
        }
        #pragma unroll
        for (int i = 0; i < 2; i++) {
            int id = tid + i * 256;
            int row = id >> 5, c4 = id & 31;
            *(float4*)&Bs[row][c4 * 4] =
                *(const float4*)(Bp + (size_t)(k0 + row) * NN + c4 * 4);
        }
        __syncthreads();
        #pragma unroll
        for (int kk = 0; kk < 16; kk++) {
            float a[8], bv[8];
            *(float4*)&a[0]  = *(const float4*)&As[kk][ty * 8];
            *(float4*)&a[4]  = *(const float4*)&As[kk][ty * 8 + 4];
            *(float4*)&bv[0] = *(const float4*)&Bs[kk][tx * 8];
            *(float4*)&bv[4] = *(const float4*)&Bs[kk][tx * 8 + 4];
            #pragma unroll
            for (int i = 0; i < 8; i++)
                #pragma unroll
                for (int j = 0; j < 8; j++) acc[i][j] += a[i] * bv[j];
        }
        __syncthreads();
    }
    #pragma unroll
    for (int i = 0; i < 8; i++) {
        float* cr = Cp + (size_t)(ty * 8 + i) * NN + tx * 8;
        float4 v0 = make_float4(acc[i][0], acc[i][1], acc[i][2], acc[i][3]);
        float4 v1 = make_float4(acc[i][4], acc[i][5], acc[i][6], acc[i][7]);
        *(float4*)cr = v0;
        *(float4*)(cr + 4) = v1;
    }
}

// ---------------------------------------------------------------------------
// K4: linear attention via associativity:  y = q @ (k^T v) * 0.25, per (b,h).
// G[d',d] = popcount over n of (k bits & v bits): 16 u64 words. Exact integers.
// Then per column n: acc[d] += q[d',n] * G[d',d]  (q in {0,1}, exact fp32).
// Grid (4 n-chunks, H, B), 256 threads = 256 n columns per block.
// ---------------------------------------------------------------------------
__global__ __launch_bounds__(256) void attn_kernel()
{
    __shared__ unsigned long long kbs[64][16];
    __shared__ unsigned long long vbs[64][16];
    __shared__ __align__(16) float Gs[64][64];

    const int nc = blockIdx.x, h = blockIdx.y, b = blockIdx.z;
    const int tid = threadIdx.x;
    const size_t base_c = (size_t)b * CC + h * DD;

    for (int i = tid; i < 64 * 16; i += 256) {
        int d = i >> 4, j = i & 15;
        kbs[d][j] = g_kb[(base_c + d) * 16 + j];
        vbs[d][j] = g_vb[(base_c + d) * 16 + j];
    }
    __syncthreads();

    for (int e = tid; e < 64 * 64; e += 256) {
        int dp = e >> 6, d = e & 63;
        int gsum = 0;
        #pragma unroll
        for (int j = 0; j < 16; j++)
            gsum += __popcll(kbs[dp][j] & vbs[d][j]);
        Gs[dp][d] = (float)gsum;
    }
    __syncthreads();

    const int n = nc * 256 + tid;
    const float* qb = g_sq + base_c * NN + n;

    float acc[64];
    #pragma unroll
    for (int d = 0; d < 64; d++) acc[d] = 0.0f;

    #pragma unroll 4
    for (int dp = 0; dp < 64; dp++) {
        float qv = qb[(size_t)dp * NN];
        const float4* gr = (const float4*)&Gs[dp][0];
        #pragma unroll
        for (int d4 = 0; d4 < 16; d4++) {
            float4 g4 = gr[d4];
            acc[d4 * 4 + 0] += qv * g4.x;
            acc[d4 * 4 + 1] += qv * g4.y;
            acc[d4 * 4 + 2] += qv * g4.z;
            acc[d4 * 4 + 3] += qv * g4.w;
        }
    }
    #pragma unroll
    for (int d = 0; d < 64; d++)
        g_y[(base_c + d) * NN + n] = acc[d] * 0.25f;
}

// ---------------------------------------------------------------------------
// K6: projection GEMM + bias + bn_proj fused epilogue -> d_out.
// Per batch b: Out[512,1024] = bn( Wp[512,512] @ sy_b + b_proj ).
// ---------------------------------------------------------------------------
__global__ __launch_bounds__(256) void gemm_proj_kernel(
    const float* __restrict__ wp, const float* __restrict__ bias,
    const float* __restrict__ bnp, float* __restrict__ out)
{
    __shared__ __align__(16) float As[16][128];
    __shared__ __align__(16) float Bs[16][128];

    const int b  = blockIdx.z;
    const int mt = blockIdx.y;   // 0..3
    const int nt = blockIdx.x;   // 0..7
    const float* A = wp + (size_t)mt * 128 * CC;
    const float* Bp = g_sy + (size_t)b * (CC * NN) + nt * 128;
    float* Cp = out + (size_t)b * (CC * NN) + (size_t)mt * 128 * NN + nt * 128;

    const int tid = threadIdx.x;
    const int tx = tid & 15, ty = tid >> 4;

    float acc[8][8];
    #pragma unroll
    for (int i = 0; i < 8; i++)
        #pragma unroll
        for (int j = 0; j < 8; j++) acc[i][j] = 0.0f;

    for (int k0 = 0; k0 < CC; k0 += 16) {
        #pragma unroll
        for (int i = 0; i < 2; i++) {
            int id = tid * 2 + i;
            int row = id >> 2, kq = id & 3;
            float4 v = *(const float4*)(A + (size_t)row * CC + k0 + kq * 4);
            As[kq * 4 + 0][row] = v.x;
            As[kq * 4 + 1][row] = v.y;
            As[kq * 4 + 2][row] = v.z;
            As[kq * 4 + 3][row] = v.w;
        }
        #pragma unroll
        for (int i = 0; i < 2; i++) {
            int id = tid + i * 256;
            int row = id >> 5, c4 = id & 31;
            *(float4*)&Bs[row][c4 * 4] =
                *(const float4*)(Bp + (size_t)(k0 + row) * NN + c4 * 4);
        }
        __syncthreads();
        #pragma unroll
        for (int kk = 0; kk < 16; kk++) {
            float a[8], bv[8];
            *(float4*)&a[0]  = *(const float4*)&As[kk][ty * 8];
            *(float4*)&a[4]  = *(const float4*)&As[kk][ty * 8 + 4];
            *(float4*)&bv[0] = *(const float4*)&Bs[kk][tx * 8];
            *(float4*)&bv[4] = *(const float4*)&Bs[kk][tx * 8 + 4];
            #pragma unroll
            for (int i = 0; i < 8; i++)
                #pragma unroll
                for (int j = 0; j < 8; j++) acc[i][j] += a[i] * bv[j];
        }
        __syncthreads();
    }

    #pragma unroll
    for (int i = 0; i < 8; i++) {
        int o = mt * 128 + ty * 8 + i;
        float g  = bnp[o];
        float be = bnp[CC + o];
        float mu = bnp[2 * CC + o];
        float va = bnp[3 * CC + o];
        float inv = g * (1.0f / sqrtf(va + 1e-5f));
        float bi = bias[o];
        float* cr = Cp + (size_t)(ty * 8 + i) * NN + tx * 8;
        float vals[8];
        #pragma unroll
        for (int j = 0; j < 8; j++)
            vals[j] = (acc[i][j] + bi - mu) * inv + be;
        float4 v0 = make_float4(vals[0], vals[1], vals[2], vals[3]);
        float4 v1 = make_float4(vals[4], vals[5], vals[6], vals[7]);
        *(float4*)cr = v0;
        *(float4*)(cr + 4) = v1;
    }
}

// ---------------------------------------------------------------------------
// Launch
// ---------------------------------------------------------------------------
extern "C" void kernel_launch(void* const* d_in, const int* in_sizes, int n_in,
                              void* d_out, int out_size)
{
    const float* x       = (const float*)d_in[0];
    const float* bn_pre  = (const float*)d_in[1];
    const float* w_q     = (const float*)d_in[2];
    const float* bn_q    = (const float*)d_in[3];
    const float* w_k     = (const float*)d_in[4];
    const float* bn_k    = (const float*)d_in[5];
    const float* w_v     = (const float*)d_in[6];
    const float* bn_v    = (const float*)d_in[7];
    const float* w_proj  = (const float*)d_in[8];
    const float* b_proj  = (const float*)d_in[9];
    const float* bn_proj = (const float*)d_in[10];
    float* out = (float*)d_out;

    float* xq_ptr; cudaGetSymbolAddress((void**)&xq_ptr, g_xq);

    // K1: pre BN + LIF -> xq spikes
    lif_bn_kernel<<<(BB * CC) / 128, 128>>>(x, bn_pre, xq_ptr, 1.0f);

    // K2: fused QKV GEMM
    gemm_qkv_kernel<<<dim3(NN / 128, CQKV / 128, BB), 256>>>(w_q, w_k, w_v);

    // K3: per-branch BN + LIF; q -> fp32, k/v -> bitpacked
    lif_qkv_kernel<<<(BB * CQKV) / 128, 128>>>(bn_q, bn_k, bn_v);

    // K4: linear attention via G = k^T v (popcount), y = q G * 0.25
    attn_kernel<<<dim3(NN / 256, HH, BB), 256>>>();

    // K5: attn LIF (threshold 0.5, no BN)
    float* y_ptr;  cudaGetSymbolAddress((void**)&y_ptr, g_y);
    float* sy_ptr; cudaGetSymbolAddress((void**)&sy_ptr, g_sy);
    lif_bn_kernel<<<(BB * CC) / 128, 128>>>(y_ptr, nullptr, sy_ptr, 0.5f);

    // K6: projection GEMM + bias + bn_proj -> out
    gemm_proj_kernel<<<dim3(NN / 128, CC / 128, BB), 256>>>(w_proj, b_proj, bn_proj, out);
}

// round 10
// speedup vs baseline: 1.7156x; 1.7156x over previous
#include <cuda_runtime.h>
#include <cuda_bf16.h>
#include <cstdint>

// Shapes (fixed by the problem)
#define BB    8
#define CC    512
#define NN    1024
#define HH    8
#define DD    64
#define CQKV  1536
#define KE    1536   // 3-way bf16 split -> effective K

// ---------------------------------------------------------------------------
// Device scratch (allocation-free per harness rules)
// ---------------------------------------------------------------------------
__device__ __nv_bfloat16 g_xq[BB * CC * NN];         // pre-LIF spikes (bf16 0/1)
__device__ float g_z [BB * CQKV * NN];               // Wqkv @ xq (pre-BN, fp32)
__device__ float g_sq[BB * CC * NN];                 // q spikes fp32 (attn input)
__device__ unsigned long long g_kb[BB * CC * 16];    // k spikes bitpacked along n
__device__ unsigned long long g_vb[BB * CC * 16];    // v spikes bitpacked along n
__device__ float g_y [BB * CC * NN];                 // attention out * 0.25
__device__ __nv_bfloat16 g_sy[BB * CC * NN];         // attn LIF spikes (bf16 0/1)
__device__ __nv_bfloat16 g_wA[(size_t)CQKV * KE];    // [1536][1536] qkv weight splits
__device__ __nv_bfloat16 g_wP[(size_t)CC * KE];      // [512][1536]  proj weight splits

// ---------------------------------------------------------------------------
// PTX helpers
// ---------------------------------------------------------------------------
__device__ __forceinline__ void cpa16(uint32_t dst, const void* src) {
    asm volatile("cp.async.cg.shared.global [%0], [%1], 16;\n" :: "r"(dst), "l"(src));
}
__device__ __forceinline__ void cpa_commit() {
    asm volatile("cp.async.commit_group;\n");
}
__device__ __forceinline__ void ldsm4(uint32_t* r, uint32_t addr) {
    asm volatile("ldmatrix.sync.aligned.m8n8.x4.shared.b16 {%0,%1,%2,%3}, [%4];"
        : "=r"(r[0]), "=r"(r[1]), "=r"(r[2]), "=r"(r[3]) : "r"(addr));
}
__device__ __forceinline__ void ldsm4t(uint32_t* r, uint32_t addr) {
    asm volatile("ldmatrix.sync.aligned.m8n8.x4.trans.shared.b16 {%0,%1,%2,%3}, [%4];"
        : "=r"(r[0]), "=r"(r[1]), "=r"(r[2]), "=r"(r[3]) : "r"(addr));
}
__device__ __forceinline__ void mma_bf16(float* d, const uint32_t* a,
                                         uint32_t b0, uint32_t b1) {
    asm volatile(
        "mma.sync.aligned.m16n8k16.row.col.f32.bf16.bf16.f32 "
        "{%0,%1,%2,%3}, {%4,%5,%6,%7}, {%8,%9}, {%0,%1,%2,%3};"
        : "+f"(d[0]), "+f"(d[1]), "+f"(d[2]), "+f"(d[3])
        : "r"(a[0]), "r"(a[1]), "r"(a[2]), "r"(a[3]), "r"(b0), "r"(b1));
}

// ---------------------------------------------------------------------------
// Prep: 3-way bf16 split of weights. A_eff[m][s*512+k] = split_s(W[m][k]).
// ---------------------------------------------------------------------------
__global__ __launch_bounds__(256) void split_kernel(
    const float* __restrict__ wq, const float* __restrict__ wk,
    const float* __restrict__ wv, const float* __restrict__ wp)
{
    int idx = blockIdx.x * 256 + threadIdx.x;        // over 1536*512
    int m = idx >> 9, k = idx & 511;
    const float* src = (m < 512) ? wq : (m < 1024) ? wk : wv;
    float w = src[(size_t)(m & 511) * 512 + k];
    __nv_bfloat16 h1 = __float2bfloat16(w);
    float r1 = w - __bfloat162float(h1);
    __nv_bfloat16 h2 = __float2bfloat16(r1);
    float r2 = r1 - __bfloat162float(h2);
    __nv_bfloat16 h3 = __float2bfloat16(r2);
    g_wA[(size_t)m * KE + k]        = h1;
    g_wA[(size_t)m * KE + 512 + k]  = h2;
    g_wA[(size_t)m * KE + 1024 + k] = h3;
    if (m < 512) {
        float w2 = wp[(size_t)m * 512 + k];
        __nv_bfloat16 p1 = __float2bfloat16(w2);
        float s1 = w2 - __bfloat162float(p1);
        __nv_bfloat16 p2 = __float2bfloat16(s1);
        float s2 = s1 - __bfloat162float(p2);
        __nv_bfloat16 p3 = __float2bfloat16(s2);
        g_wP[(size_t)m * KE + k]        = p1;
        g_wP[(size_t)m * KE + 512 + k]  = p2;
        g_wP[(size_t)m * KE + 1024 + k] = p3;
    }
}

// ---------------------------------------------------------------------------
// bf16 tensor-core GEMM: C[b][M][1024] = A[M][1536] @ B_eff, where
// B_eff[k][n] = spikes[b][k & 511][n]  (3-way split repeats the spike matrix).
// 128x128 block tile, BK=32, 256 threads, 8 warps (4m x 2n), warp tile 32x64.
// cp.async double buffered; ldmatrix; mma.sync m16n8k16 bf16 -> fp32.
// EPI: fused bias + BN epilogue (proj); else raw fp32 store (qkv).
// ---------------------------------------------------------------------------
#define BM 128
#define BN 128
#define BK 32
#define KT (KE / BK)          // 48
#define ASZ (BM * 40 * 2)     // bytes per A stage (pad to 40 halves/row)
#define BSZ (BK * BN * 2)     // bytes per B stage

template<bool EPI>
__global__ __launch_bounds__(256) void gemm_bf16_kernel(
    const __nv_bfloat16* __restrict__ A,    // [M][KE] row-major
    const __nv_bfloat16* __restrict__ Bsp,  // [BB][512][1024] spikes
    float* __restrict__ C,                  // [BB][M][1024]
    int M,
    const float* __restrict__ bias, const float* __restrict__ bnp)
{
    __shared__ __align__(16) __nv_bfloat16 As[2][BM][40];
    __shared__ __align__(16) __nv_bfloat16 Bs[2][BK][BN];

    const int b  = blockIdx.z;
    const int mt = blockIdx.y;
    const int nt = blockIdx.x;
    const int tid  = threadIdx.x;
    const int lane = tid & 31;
    const int warp = tid >> 5;
    const int wm = warp & 3;       // 4 m-warps of 32 rows
    const int wn = warp >> 2;      // 2 n-warps of 64 cols

    const __nv_bfloat16* Ag = A + (size_t)mt * BM * KE;
    const __nv_bfloat16* Bg = Bsp + (size_t)b * (512 * 1024) + nt * BN;

    const uint32_t asBase = (uint32_t)__cvta_generic_to_shared(&As[0][0][0]);
    const uint32_t bsBase = (uint32_t)__cvta_generic_to_shared(&Bs[0][0][0]);

    float acc[2][8][4];
    #pragma unroll
    for (int i = 0; i < 2; i++)
        #pragma unroll
        for (int j = 0; j < 8; j++)
            #pragma unroll
            for (int r = 0; r < 4; r++) acc[i][j][r] = 0.0f;

    // ---- stage loader ----
    auto load_stage = [&](int buf, int k0) {
        #pragma unroll
        for (int i = 0; i < 2; i++) {
            int id = tid * 2 + i;
            // A: 512 chunks of 16B: row = id>>2, chunk = id&3
            int ar = id >> 2, ac = id & 3;
            cpa16(asBase + buf * ASZ + ar * 80 + ac * 16,
                  Ag + (size_t)ar * KE + k0 + ac * 8);
            // B: 512 chunks: row = id>>4, chunk = id&15 (XOR swizzle)
            int br = id >> 4, bc = id & 15;
            int kph = (k0 + br) & 511;
            cpa16(bsBase + buf * BSZ + br * 256 + ((bc ^ (br & 7)) << 4),
                  Bg + (size_t)kph * 1024 + bc * 8);
        }
        cpa_commit();
    };

    load_stage(0, 0);

    for (int kt = 0; kt < KT; kt++) {
        if (kt + 1 < KT) {
            load_stage((kt + 1) & 1, (kt + 1) * BK);
            asm volatile("cp.async.wait_group 1;\n");
        } else {
            asm volatile("cp.async.wait_group 0;\n");
        }
        __syncthreads();

        const int buf = kt & 1;
        const uint32_t aB = asBase + buf * ASZ;
        const uint32_t bB = bsBase + buf * BSZ;

        #pragma unroll
        for (int k16 = 0; k16 < 2; k16++) {
            uint32_t afr[2][4], bfr[4][4];
            #pragma unroll
            for (int mi = 0; mi < 2; mi++) {
                int row = wm * 32 + mi * 16 + (lane & 15);
                ldsm4(afr[mi], aB + row * 80 + k16 * 32 + ((lane >> 4) << 4));
            }
            #pragma unroll
            for (int ni = 0; ni < 4; ni++) {
                int row = k16 * 16 + (lane & 15);
                int col = wn * 64 + ni * 16 + ((lane >> 4) << 3);
                int c = col >> 3;
                ldsm4t(bfr[ni], bB + row * 256 + ((c ^ (row & 7)) << 4));
            }
            #pragma unroll
            for (int mi = 0; mi < 2; mi++)
                #pragma unroll
                for (int j = 0; j < 8; j++)
                    mma_bf16(acc[mi][j], afr[mi],
                             bfr[j >> 1][(j & 1) * 2], bfr[j >> 1][(j & 1) * 2 + 1]);
        }
        __syncthreads();
    }

    // ---- epilogue ----
    #pragma unroll
    for (int mi = 0; mi < 2; mi++) {
        #pragma unroll
        for (int r = 0; r < 2; r++) {
            int grow = mt * 128 + wm * 32 + mi * 16 + (lane >> 2) + r * 8;
            float* crow = C + (size_t)b * M * 1024 + (size_t)grow * 1024
                          + nt * 128 + wn * 64 + (lane & 3) * 2;
            float inv = 1.0f, mu = 0.0f, be = 0.0f, bi = 0.0f;
            if (EPI) {
                float g  = bnp[grow];
                be = bnp[512 + grow];
                mu = bnp[1024 + grow];
                float va = bnp[1536 + grow];
                inv = g * rsqrtf(va + 1e-5f);
                bi = bias[grow];
            }
            #pragma unroll
            for (int j = 0; j < 8; j++) {
                float v0 = acc[mi][j][r * 2];
                float v1 = acc[mi][j][r * 2 + 1];
                if (EPI) {
                    v0 = (v0 + bi - mu) * inv + be;
                    v1 = (v1 + bi - mu) * inv + be;
                }
                *(float2*)(crow + j * 8) = make_float2(v0, v1);
            }
        }
    }
}

// ---------------------------------------------------------------------------
// K1 / K5: (optional BN) + LIF scan over N, templated output type.
// ---------------------------------------------------------------------------
template<typename OutT>
__global__ __launch_bounds__(128) void lif_bn_kernel(
    const float* __restrict__ in, const float* __restrict__ bnp,
    OutT* __restrict__ out, float vth)
{
    __shared__ float tile[128][33];
    const int tid = threadIdx.x;
    const int r0  = blockIdx.x * 128;
    const int row = r0 + tid;

    float inv = 1.0f, mu = 0.0f, be = 0.0f;
    if (bnp) {
        int c = row & (CC - 1);
        float g  = bnp[c];
        float bb = bnp[CC + c];
        float m  = bnp[2 * CC + c];
        float va = bnp[3 * CC + c];
        inv = g * (1.0f / sqrtf(va + 1e-5f));
        mu = m; be = bb;
    }

    const int lr0 = tid >> 5;
    const int col = tid & 31;
    float v = 0.0f;

    for (int t = 0; t < NN / 32; t++) {
        for (int p = 0; p < 32; p++) {
            int lr = lr0 + p * 4;
            tile[lr][col] = in[(size_t)(r0 + lr) * NN + t * 32 + col];
        }
        __syncthreads();
        #pragma unroll
        for (int kk = 0; kk < 32; kk++) {
            float xb = (tile[tid][kk] - mu) * inv + be;
            v = v + (xb - v) * 0.5f;
            bool sp = (v >= vth);
            tile[tid][kk] = sp ? 1.0f : 0.0f;
            v = sp ? 0.0f : v;
        }
        __syncthreads();
        for (int p = 0; p < 32; p++) {
            int lr = lr0 + p * 4;
            out[(size_t)(r0 + lr) * NN + t * 32 + col] = (OutT)tile[lr][col];
        }
        __syncthreads();
    }
}

// ---------------------------------------------------------------------------
// K3: per-branch BN + LIF on stacked QKV output; q -> fp32, k/v -> bitpacked.
// ---------------------------------------------------------------------------
__global__ __launch_bounds__(128) void lif_qkv_kernel(
    const float* __restrict__ bnq, const float* __restrict__ bnk,
    const float* __restrict__ bnv)
{
    __shared__ float tile[128][33];
    const int tid = threadIdx.x;
    const int r0  = blockIdx.x * 128;
    const int b   = r0 / CQKV;
    const int o0  = r0 % CQKV;
    const int branch = o0 / CC;
    const int c0  = o0 % CC;

    const float* bnp = (branch == 0) ? bnq : (branch == 1) ? bnk : bnv;
    const int c = c0 + tid;
    float g  = bnp[c];
    float be = bnp[CC + c];
    float mu = bnp[2 * CC + c];
    float va = bnp[3 * CC + c];
    float inv = g * (1.0f / sqrtf(va + 1e-5f));

    const float* inbase = g_z + (size_t)r0 * NN;
    float* outq = g_sq + ((size_t)b * CC + c0) * NN;
    unsigned long long* outb = (branch == 1) ? g_kb : g_vb;
    const size_t brow = ((size_t)b * CC + c) * 16;

    const int lr0 = tid >> 5;
    const int col = tid & 31;
    float v = 0.0f;
    unsigned long long cur = 0ull;

    for (int t = 0; t < NN / 32; t++) {
        for (int p = 0; p < 32; p++) {
            int lr = lr0 + p * 4;
            tile[lr][col] = inbase[(size_t)lr * NN + t * 32 + col];
        }
        __syncthreads();
        const int bitbase = (t & 1) << 5;
        #pragma unroll
        for (int kk = 0; kk < 32; kk++) {
            float xb = (tile[tid][kk] - mu) * inv + be;
            v = v + (xb - v) * 0.5f;
            bool sp = (v >= 1.0f);
            tile[tid][kk] = sp ? 1.0f : 0.0f;
            if (sp) cur |= 1ull << (bitbase + kk);
            v = sp ? 0.0f : v;
        }
        __syncthreads();
        if (branch == 0) {
            for (int p = 0; p < 32; p++) {
                int lr = lr0 + p * 4;
                outq[(size_t)lr * NN + t * 32 + col] = tile[lr][col];
            }
        } else if (t & 1) {
            outb[brow + (t >> 1)] = cur;
            cur = 0ull;
        }
        __syncthreads();
    }
}

// ---------------------------------------------------------------------------
// K4: linear attention via associativity: y = q @ (k^T v) * 0.25, per (b,h).
// ---------------------------------------------------------------------------
__global__ __launch_bounds__(256) void attn_kernel()
{
    __shared__ unsigned long long kbs[64][16];
    __shared__ unsigned long long vbs[64][16];
    __shared__ __align__(16) float Gs[64][64];

    const int nc = blockIdx.x, h = blockIdx.y, b = blockIdx.z;
    const int tid = threadIdx.x;
    const size_t base_c = (size_t)b * CC + h * DD;

    for (int i = tid; i < 64 * 16; i += 256) {
        int d = i >> 4, j = i & 15;
        kbs[d][j] = g_kb[(base_c + d) * 16 + j];
        vbs[d][j] = g_vb[(base_c + d) * 16 + j];
    }
    __syncthreads();

    for (int e = tid; e < 64 * 64; e += 256) {
        int dp = e >> 6, d = e & 63;
        int gsum = 0;
        #pragma unroll
        for (int j = 0; j < 16; j++)
            gsum += __popcll(kbs[dp][j] & vbs[d][j]);
        Gs[dp][d] = (float)gsum;
    }
    __syncthreads();

    const int n = nc * 256 + tid;
    const float* qb = g_sq + base_c * NN + n;

    float acc[64];
    #pragma unroll
    for (int d = 0; d < 64; d++) acc[d] = 0.0f;

    #pragma unroll 4
    for (int dp = 0; dp < 64; dp++) {
        float qv = qb[(size_t)dp * NN];
        const float4* gr = (const float4*)&Gs[dp][0];
        #pragma unroll
        for (int d4 = 0; d4 < 16; d4++) {
            float4 g4 = gr[d4];
            acc[d4 * 4 + 0] += qv * g4.x;
            acc[d4 * 4 + 1] += qv * g4.y;
            acc[d4 * 4 + 2] += qv * g4.z;
            acc[d4 * 4 + 3] += qv * g4.w;
        }
    }
    #pragma unroll
    for (int d = 0; d < 64; d++)
        g_y[(base_c + d) * NN + n] = acc[d] * 0.25f;
}

// ---------------------------------------------------------------------------
// Launch
// ---------------------------------------------------------------------------
extern "C" void kernel_launch(void* const* d_in, const int* in_sizes, int n_in,
                              void* d_out, int out_size)
{
    const float* x       = (const float*)d_in[0];
    const float* bn_pre  = (const float*)d_in[1];
    const float* w_q     = (const float*)d_in[2];
    const float* bn_q    = (const float*)d_in[3];
    const float* w_k     = (const float*)d_in[4];
    const float* bn_k    = (const float*)d_in[5];
    const float* w_v     = (const float*)d_in[6];
    const float* bn_v    = (const float*)d_in[7];
    const float* w_proj  = (const float*)d_in[8];
    const float* b_proj  = (const float*)d_in[9];
    const float* bn_proj = (const float*)d_in[10];
    float* out = (float*)d_out;

    __nv_bfloat16* xq_ptr; cudaGetSymbolAddress((void**)&xq_ptr, g_xq);
    __nv_bfloat16* sy_ptr; cudaGetSymbolAddress((void**)&sy_ptr, g_sy);
    __nv_bfloat16* wA_ptr; cudaGetSymbolAddress((void**)&wA_ptr, g_wA);
    __nv_bfloat16* wP_ptr; cudaGetSymbolAddress((void**)&wP_ptr, g_wP);
    float* z_ptr;  cudaGetSymbolAddress((void**)&z_ptr, g_z);
    float* y_ptr;  cudaGetSymbolAddress((void**)&y_ptr, g_y);

    // P0: 3-way bf16 weight splits
    split_kernel<<<(CQKV * CC) / 256, 256>>>(w_q, w_k, w_v, w_proj);

    // K1: pre BN + LIF -> xq spikes (bf16)
    lif_bn_kernel<__nv_bfloat16><<<(BB * CC) / 128, 128>>>(x, bn_pre, xq_ptr, 1.0f);

    // K2: fused QKV GEMM (tensor cores, bf16 split)
    gemm_bf16_kernel<false><<<dim3(NN / BN, CQKV / BM, BB), 256>>>(
        wA_ptr, xq_ptr, z_ptr, CQKV, nullptr, nullptr);

    // K3: per-branch BN + LIF; q -> fp32, k/v -> bitpacked
    lif_qkv_kernel<<<(BB * CQKV) / 128, 128>>>(bn_q, bn_k, bn_v);

    // K4: linear attention via G = k^T v (popcount), y = q G * 0.25
    attn_kernel<<<dim3(NN / 256, HH, BB), 256>>>();

    // K5: attn LIF (threshold 0.5, no BN) -> sy spikes (bf16)
    lif_bn_kernel<__nv_bfloat16><<<(BB * CC) / 128, 128>>>(y_ptr, nullptr, sy_ptr, 0.5f);

    // K6: projection GEMM + bias + bn_proj fused epilogue -> out
    gemm_bf16_kernel<true><<<dim3(NN / BN, CC / BM, BB), 256>>>(
        wP_ptr, sy_ptr, out, CC, b_proj, bn_proj);
}

// round 11
// speedup vs baseline: 2.2322x; 1.3012x over previous
#include <cuda_runtime.h>
#include <cuda_bf16.h>
#include <cstdint>

typedef unsigned long long u64;
typedef unsigned int u32;

// Shapes (fixed by the problem)
#define BB    8
#define CC    512
#define NN    1024
#define HH    8
#define DD    64
#define CQKV  1536

// ---------------------------------------------------------------------------
// Device scratch (allocation-free per harness rules)
// ---------------------------------------------------------------------------
__device__ __nv_bfloat16 g_xq[BB * CC * NN];         // pre-LIF spikes (bf16 0/1)
__device__ float g_z [BB * CQKV * NN];               // Wqkv @ xq (pre-BN, fp32)
__device__ __nv_bfloat16 g_sqh[BB * CC * NN];        // q spikes bf16
__device__ u64 g_kb[BB * CC * 16];                   // k spikes bitpacked along n
__device__ u64 g_vb[BB * CC * 16];                   // v spikes bitpacked along n
__device__ float g_y [BB * CC * NN];                 // attention out * 0.25
__device__ __nv_bfloat16 g_sy[BB * CC * NN];         // attn LIF spikes (bf16 0/1)
__device__ __nv_bfloat16 g_wA[3 * CQKV * CC];        // [3][1536][512] qkv splits
__device__ __nv_bfloat16 g_wP[3 * CC * CC];          // [3][512][512]  proj splits

// ---------------------------------------------------------------------------
// PTX helpers
// ---------------------------------------------------------------------------
__device__ __forceinline__ void cpa16(u32 dst, const void* src) {
    asm volatile("cp.async.cg.shared.global [%0], [%1], 16;\n" :: "r"(dst), "l"(src));
}
__device__ __forceinline__ void cpa_commit() {
    asm volatile("cp.async.commit_group;\n");
}
__device__ __forceinline__ void ldsm4(u32* r, u32 addr) {
    asm volatile("ldmatrix.sync.aligned.m8n8.x4.shared.b16 {%0,%1,%2,%3}, [%4];"
        : "=r"(r[0]), "=r"(r[1]), "=r"(r[2]), "=r"(r[3]) : "r"(addr));
}
__device__ __forceinline__ void ldsm4t(u32* r, u32 addr) {
    asm volatile("ldmatrix.sync.aligned.m8n8.x4.trans.shared.b16 {%0,%1,%2,%3}, [%4];"
        : "=r"(r[0]), "=r"(r[1]), "=r"(r[2]), "=r"(r[3]) : "r"(addr));
}
__device__ __forceinline__ void mma_bf16(float* d, const u32* a, u32 b0, u32 b1) {
    asm volatile(
        "mma.sync.aligned.m16n8k16.row.col.f32.bf16.bf16.f32 "
        "{%0,%1,%2,%3}, {%4,%5,%6,%7}, {%8,%9}, {%0,%1,%2,%3};"
        : "+f"(d[0]), "+f"(d[1]), "+f"(d[2]), "+f"(d[3])
        : "r"(a[0]), "r"(a[1]), "r"(a[2]), "r"(a[3]), "r"(b0), "r"(b1));
}

// ---------------------------------------------------------------------------
// Prep: 3-way bf16 split of weights, layout [split][m][k].
// ---------------------------------------------------------------------------
__global__ __launch_bounds__(256) void split_kernel(
    const float* __restrict__ wq, const float* __restrict__ wk,
    const float* __restrict__ wv, const float* __restrict__ wp)
{
    int idx = blockIdx.x * 256 + threadIdx.x;        // over 1536*512
    int m = idx >> 9, k = idx & 511;
    const float* src = (m < 512) ? wq : (m < 1024) ? wk : wv;
    float w = src[(size_t)(m & 511) * 512 + k];
    __nv_bfloat16 h1 = __float2bfloat16(w);
    float r1 = w - __bfloat162float(h1);
    __nv_bfloat16 h2 = __float2bfloat16(r1);
    float r2 = r1 - __bfloat162float(h2);
    __nv_bfloat16 h3 = __float2bfloat16(r2);
    g_wA[(size_t)m * 512 + k]                    = h1;
    g_wA[(size_t)(CQKV + m) * 512 + k]           = h2;
    g_wA[(size_t)(2 * CQKV + m) * 512 + k]       = h3;
    if (m < 512) {
        float w2 = wp[(size_t)m * 512 + k];
        __nv_bfloat16 p1 = __float2bfloat16(w2);
        float s1 = w2 - __bfloat162float(p1);
        __nv_bfloat16 p2 = __float2bfloat16(s1);
        float s2 = s1 - __bfloat162float(p2);
        __nv_bfloat16 p3 = __float2bfloat16(s2);
        g_wP[(size_t)m * 512 + k]              = p1;
        g_wP[(size_t)(CC + m) * 512 + k]       = p2;
        g_wP[(size_t)(2 * CC + m) * 512 + k]   = p3;
    }
}

// ---------------------------------------------------------------------------
// GEMM v2: C[b][M][1024] = sum_s A_s[M][512] @ spikes[b][512][1024].
// K-loop over 512 with BK=32; per stage ONE shared B tile + THREE A tiles
// (3-way split) -> B smem traffic /3. 3-stage cp.async pipeline, dynamic smem.
// 128x128 block tile, 256 thr, 8 warps (4m x 2n), warp tile 32x64, mma bf16.
// ---------------------------------------------------------------------------
#define ASTG (128 * 80)          // 10240 B per A split per stage (pad 80B/row)
#define A3SZ (3 * ASTG)          // 30720
#define BSTG (32 * 256)          // 8192
#define STGB (A3SZ + BSTG)       // 38912
#define GSMEM (3 * STGB)         // 116736 dynamic smem

template<bool EPI>
__global__ __launch_bounds__(256) void gemm3_kernel(
    const __nv_bfloat16* __restrict__ W,     // [3][M][512]
    const __nv_bfloat16* __restrict__ Bsp,   // [BB][512][1024] spikes
    float* __restrict__ C, int M,
    const float* __restrict__ bias, const float* __restrict__ bnp)
{
    extern __shared__ __align__(16) char smem[];
    const u32 smemBase = (u32)__cvta_generic_to_shared(smem);

    const int b  = blockIdx.z;
    const int mt = blockIdx.y;
    const int nt = blockIdx.x;
    const int tid  = threadIdx.x;
    const int lane = tid & 31;
    const int warp = tid >> 5;
    const int wm = warp & 3;
    const int wn = warp >> 2;

    const __nv_bfloat16* Bg = Bsp + (size_t)b * (512 * 1024) + nt * 128;

    float acc[2][8][4];
    #pragma unroll
    for (int i = 0; i < 2; i++)
        #pragma unroll
        for (int j = 0; j < 8; j++)
            #pragma unroll
            for (int r = 0; r < 4; r++) acc[i][j][r] = 0.0f;

    auto load_stage = [&](int st, int k0) {
        u32 sb = smemBase + st * STGB;
        #pragma unroll
        for (int s = 0; s < 3; s++) {
            #pragma unroll
            for (int j = 0; j < 2; j++) {
                int idx = tid * 2 + j;                 // 0..511
                int ar = idx >> 2, ac = idx & 3;
                cpa16(sb + s * ASTG + ar * 80 + ac * 16,
                      W + ((size_t)(s * M + mt * 128 + ar)) * 512 + k0 + ac * 8);
            }
        }
        #pragma unroll
        for (int j = 0; j < 2; j++) {
            int idx = tid + j * 256;                   // 0..511
            int br = idx >> 4, bc = idx & 15;
            cpa16(sb + A3SZ + br * 256 + ((bc ^ (br & 7)) << 4),
                  Bg + (size_t)(k0 + br) * 1024 + bc * 8);
        }
        cpa_commit();
    };

    load_stage(0, 0);
    load_stage(1, 32);

    for (int kt = 0; kt < 16; kt++) {
        if (kt + 2 < 16) load_stage((kt + 2) % 3, (kt + 2) * 32);
        else             cpa_commit();                 // keep group count uniform
        asm volatile("cp.async.wait_group 2;\n");
        __syncthreads();

        const u32 aB = smemBase + (kt % 3) * STGB;
        const u32 bB = aB + A3SZ;

        #pragma unroll
        for (int k16 = 0; k16 < 2; k16++) {
            u32 bfr[4][4];
            #pragma unroll
            for (int ni = 0; ni < 4; ni++) {
                int row = k16 * 16 + (lane & 15);
                int col = wn * 64 + ni * 16 + ((lane >> 4) << 3);
                int c = col >> 3;
                ldsm4t(bfr[ni], bB + row * 256 + ((c ^ (row & 7)) << 4));
            }
            #pragma unroll
            for (int s = 0; s < 3; s++) {
                u32 afr[2][4];
                #pragma unroll
                for (int mi = 0; mi < 2; mi++) {
                    int row = wm * 32 + mi * 16 + (lane & 15);
                    ldsm4(afr[mi], aB + s * ASTG + row * 80 + k16 * 32
                                   + ((lane >> 4) << 4));
                }
                #pragma unroll
                for (int mi = 0; mi < 2; mi++)
                    #pragma unroll
                    for (int j = 0; j < 8; j++)
                        mma_bf16(acc[mi][j], afr[mi],
                                 bfr[j >> 1][(j & 1) * 2],
                                 bfr[j >> 1][(j & 1) * 2 + 1]);
            }
        }
        __syncthreads();
    }

    // epilogue
    #pragma unroll
    for (int mi = 0; mi < 2; mi++) {
        #pragma unroll
        for (int r = 0; r < 2; r++) {
            int grow = mt * 128 + wm * 32 + mi * 16 + (lane >> 2) + r * 8;
            float* crow = C + (size_t)b * M * 1024 + (size_t)grow * 1024
                          + nt * 128 + wn * 64 + (lane & 3) * 2;
            float inv = 1.0f, mu = 0.0f, be = 0.0f, bi = 0.0f;
            if (EPI) {
                float g  = bnp[grow];
                be = bnp[512 + grow];
                mu = bnp[1024 + grow];
                float va = bnp[1536 + grow];
                inv = g * rsqrtf(va + 1e-5f);
                bi = bias[grow];
            }
            #pragma unroll
            for (int j = 0; j < 8; j++) {
                float v0 = acc[mi][j][r * 2];
                float v1 = acc[mi][j][r * 2 + 1];
                if (EPI) {
                    v0 = (v0 + bi - mu) * inv + be;
                    v1 = (v1 + bi - mu) * inv + be;
                }
                *(float2*)(crow + j * 8) = make_float2(v0, v1);
            }
        }
    }
}

// ---------------------------------------------------------------------------
// LIF v2 (K1/K5): warp-private 32-row tiles, float4 register prefetch
// overlapping the scan, __syncwarp only, packed bf16 spike stores.
// ---------------------------------------------------------------------------
__global__ __launch_bounds__(128) void lif2_kernel(
    const float* __restrict__ in, const float* __restrict__ bnp,
    __nv_bfloat16* __restrict__ out, float vth)
{
    __shared__ float buf[4][32][33];
    const int lane = threadIdx.x & 31;
    const int w    = threadIdx.x >> 5;
    const int r0   = blockIdx.x * 128 + w * 32;
    const int row  = r0 + lane;

    float inv = 1.0f, mu = 0.0f, be = 0.0f;
    if (bnp) {
        int c = row & (CC - 1);
        inv = bnp[c] * (1.0f / sqrtf(bnp[3 * CC + c] + 1e-5f));
        be  = bnp[CC + c];
        mu  = bnp[2 * CC + c];
    }

    const float* src = in + (size_t)r0 * NN;
    __nv_bfloat16* dst = out + (size_t)row * NN;

    float4 nxt[8];
    #pragma unroll
    for (int i = 0; i < 8; i++) {
        int f = lane + 32 * i;
        nxt[i] = *(const float4*)(src + (size_t)(f >> 3) * NN + (f & 7) * 4);
    }

    float v = 0.0f;
    for (int t = 0; t < 32; t++) {
        #pragma unroll
        for (int i = 0; i < 8; i++) {
            int f = lane + 32 * i;
            int r = f >> 3, c0 = (f & 7) * 4;
            buf[w][r][c0 + 0] = nxt[i].x;
            buf[w][r][c0 + 1] = nxt[i].y;
            buf[w][r][c0 + 2] = nxt[i].z;
            buf[w][r][c0 + 3] = nxt[i].w;
        }
        __syncwarp();
        if (t + 1 < 32) {
            #pragma unroll
            for (int i = 0; i < 8; i++) {
                int f = lane + 32 * i;
                nxt[i] = *(const float4*)(src + (size_t)(f >> 3) * NN
                                          + (t + 1) * 32 + (f & 7) * 4);
            }
        }
        u32 pk[16];
        #pragma unroll
        for (int kk = 0; kk < 32; kk++) {
            float x  = buf[w][lane][kk];
            float xb = (x - mu) * inv + be;
            v = v + (xb - v) * 0.5f;
            bool sp = (v >= vth);
            v = sp ? 0.0f : v;
            u32 sb = sp ? 0x3F80u : 0u;
            if (kk & 1) pk[kk >> 1] |= sb << 16;
            else        pk[kk >> 1]  = sb;
        }
        __syncwarp();
        #pragma unroll
        for (int j = 0; j < 4; j++) {
            uint4 q = make_uint4(pk[j*4], pk[j*4+1], pk[j*4+2], pk[j*4+3]);
            *(uint4*)(dst + t * 32 + j * 8) = q;
        }
    }
}

// ---------------------------------------------------------------------------
// LIF v2 (K3): BN per branch; q -> bf16 spikes, k/v -> bitpacked.
// ---------------------------------------------------------------------------
__global__ __launch_bounds__(128) void lif_qkv2_kernel(
    const float* __restrict__ bnq, const float* __restrict__ bnk,
    const float* __restrict__ bnv)
{
    __shared__ float buf[4][32][33];
    const int lane = threadIdx.x & 31;
    const int w    = threadIdx.x >> 5;
    const int r0g  = blockIdx.x * 128 + w * 32;
    const int b    = r0g / CQKV;
    const int o    = r0g % CQKV;
    const int br   = o >> 9;
    const int c    = (o & 511) + lane;

    const float* bnp = (br == 0) ? bnq : (br == 1) ? bnk : bnv;
    float inv = bnp[c] * (1.0f / sqrtf(bnp[3 * CC + c] + 1e-5f));
    float be  = bnp[CC + c];
    float mu  = bnp[2 * CC + c];

    const float* src = g_z + (size_t)r0g * NN;
    __nv_bfloat16* qdst = g_sqh + ((size_t)b * CC + c) * NN;
    u64* bdst = ((br == 1) ? g_kb : g_vb) + ((size_t)b * CC + c) * 16;

    float4 nxt[8];
    #pragma unroll
    for (int i = 0; i < 8; i++) {
        int f = lane + 32 * i;
        nxt[i] = *(const float4*)(src + (size_t)(f >> 3) * NN + (f & 7) * 4);
    }

    float v = 0.0f;
    u32 prevbits = 0;
    for (int t = 0; t < 32; t++) {
        #pragma unroll
        for (int i = 0; i < 8; i++) {
            int f = lane + 32 * i;
            int r = f >> 3, c0 = (f & 7) * 4;
            buf[w][r][c0 + 0] = nxt[i].x;
            buf[w][r][c0 + 1] = nxt[i].y;
            buf[w][r][c0 + 2] = nxt[i].z;
            buf[w][r][c0 + 3] = nxt[i].w;
        }
        __syncwarp();
        if (t + 1 < 32) {
            #pragma unroll
            for (int i = 0; i < 8; i++) {
                int f = lane + 32 * i;
                nxt[i] = *(const float4*)(src + (size_t)(f >> 3) * NN
                                          + (t + 1) * 32 + (f & 7) * 4);
            }
        }
        u32 pk[16];
        u32 tb = 0;
        #pragma unroll
        for (int kk = 0; kk < 32; kk++) {
            float x  = buf[w][lane][kk];
            float xb = (x - mu) * inv + be;
            v = v + (xb - v) * 0.5f;
            bool sp = (v >= 1.0f);
            v = sp ? 0.0f : v;
            if (br == 0) {
                u32 sb = sp ? 0x3F80u : 0u;
                if (kk & 1) pk[kk >> 1] |= sb << 16;
                else        pk[kk >> 1]  = sb;
            } else {
                tb |= (sp ? 1u : 0u) << kk;
            }
        }
        __syncwarp();
        if (br == 0) {
            #pragma unroll
            for (int j = 0; j < 4; j++) {
                uint4 q = make_uint4(pk[j*4], pk[j*4+1], pk[j*4+2], pk[j*4+3]);
                *(uint4*)(qdst + t * 32 + j * 8) = q;
            }
        } else {
            if (t & 1) bdst[t >> 1] = ((u64)tb << 32) | (u64)prevbits;
            else       prevbits = tb;
        }
    }
}

// ---------------------------------------------------------------------------
// attn v2: y = q @ (k^T v) * 0.25 per (b,h), d-split x2 for occupancy.
// G via popcount on bitpacked k/v; q read as bf16 spikes.
// ---------------------------------------------------------------------------
__global__ __launch_bounds__(256) void attn2_kernel()
{
    __shared__ u64 kbs[64][16];
    __shared__ u64 vbs[32][16];
    __shared__ __align__(16) float Gs[64][32];

    const int nc = blockIdx.x;
    const int h  = blockIdx.y >> 1;
    const int dh = blockIdx.y & 1;
    const int b  = blockIdx.z;
    const int tid = threadIdx.x;
    const size_t base_c = (size_t)b * CC + h * DD;

    for (int i = tid; i < 64 * 16; i += 256) {
        int d = i >> 4, j = i & 15;
        kbs[d][j] = g_kb[(base_c + d) * 16 + j];
    }
    for (int i = tid; i < 32 * 16; i += 256) {
        int d = i >> 4, j = i & 15;
        vbs[d][j] = g_vb[(base_c + dh * 32 + d) * 16 + j];
    }
    __syncthreads();

    for (int e = tid; e < 64 * 32; e += 256) {
        int dp = e >> 5, dd = e & 31;
        int gsum = 0;
        #pragma unroll
        for (int j = 0; j < 16; j++)
            gsum += __popcll(kbs[dp][j] & vbs[dd][j]);
        Gs[dp][dd] = (float)gsum;
    }
    __syncthreads();

    const int n = nc * 256 + tid;
    const __nv_bfloat16* qb = g_sqh + base_c * NN + n;

    float acc[32];
    #pragma unroll
    for (int d = 0; d < 32; d++) acc[d] = 0.0f;

    #pragma unroll 4
    for (int dp = 0; dp < 64; dp++) {
        float qv = __bfloat162float(qb[(size_t)dp * NN]);
        const float4* gr = (const float4*)&Gs[dp][0];
        #pragma unroll
        for (int j = 0; j < 8; j++) {
            float4 g4 = gr[j];
            acc[j * 4 + 0] += qv * g4.x;
            acc[j * 4 + 1] += qv * g4.y;
            acc[j * 4 + 2] += qv * g4.z;
            acc[j * 4 + 3] += qv * g4.w;
        }
    }
    #pragma unroll
    for (int d = 0; d < 32; d++)
        g_y[(base_c + dh * 32 + d) * NN + n] = acc[d] * 0.25f;
}

// ---------------------------------------------------------------------------
// Launch
// ---------------------------------------------------------------------------
extern "C" void kernel_launch(void* const* d_in, const int* in_sizes, int n_in,
                              void* d_out, int out_size)
{
    const float* x       = (const float*)d_in[0];
    const float* bn_pre  = (const float*)d_in[1];
    const float* w_q     = (const float*)d_in[2];
    const float* bn_q    = (const float*)d_in[3];
    const float* w_k     = (const float*)d_in[4];
    const float* bn_k    = (const float*)d_in[5];
    const float* w_v     = (const float*)d_in[6];
    const float* bn_v    = (const float*)d_in[7];
    const float* w_proj  = (const float*)d_in[8];
    const float* b_proj  = (const float*)d_in[9];
    const float* bn_proj = (const float*)d_in[10];
    float* out = (float*)d_out;

    __nv_bfloat16* xq_ptr; cudaGetSymbolAddress((void**)&xq_ptr, g_xq);
    __nv_bfloat16* sy_ptr; cudaGetSymbolAddress((void**)&sy_ptr, g_sy);
    __nv_bfloat16* wA_ptr; cudaGetSymbolAddress((void**)&wA_ptr, g_wA);
    __nv_bfloat16* wP_ptr; cudaGetSymbolAddress((void**)&wP_ptr, g_wP);
    float* z_ptr;  cudaGetSymbolAddress((void**)&z_ptr, g_z);
    float* y_ptr;  cudaGetSymbolAddress((void**)&y_ptr, g_y);

    cudaFuncSetAttribute(gemm3_kernel<false>,
                         cudaFuncAttributeMaxDynamicSharedMemorySize, GSMEM);
    cudaFuncSetAttribute(gemm3_kernel<true>,
                         cudaFuncAttributeMaxDynamicSharedMemorySize, GSMEM);

    // P0: 3-way bf16 weight splits, [s][m][k]
    split_kernel<<<(CQKV * CC) / 256, 256>>>(w_q, w_k, w_v, w_proj);

    // K1: pre BN + LIF -> xq spikes (bf16)
    lif2_kernel<<<(BB * CC) / 128, 128>>>(x, bn_pre, xq_ptr, 1.0f);

    // K2: fused QKV GEMM (tensor cores, shared-B 3-split)
    gemm3_kernel<false><<<dim3(8, 12, 8), 256, GSMEM>>>(
        wA_ptr, xq_ptr, z_ptr, CQKV, nullptr, nullptr);

    // K3: per-branch BN + LIF; q -> bf16, k/v -> bitpacked
    lif_qkv2_kernel<<<(BB * CQKV) / 128, 128>>>(bn_q, bn_k, bn_v);

    // K4: linear attention via G = k^T v (popcount), y = q G * 0.25
    attn2_kernel<<<dim3(4, 16, 8), 256>>>();

    // K5: attn LIF (threshold 0.5, no BN) -> sy spikes (bf16)
    lif2_kernel<<<(BB * CC) / 128, 128>>>(y_ptr, nullptr, sy_ptr, 0.5f);

    // K6: projection GEMM + bias + bn_proj fused epilogue -> out
    gemm3_kernel<true><<<dim3(8, 4, 8), 256, GSMEM>>>(
        wP_ptr, sy_ptr, out, CC, b_proj, bn_proj);
}

// round 12
// speedup vs baseline: 2.7010x; 1.2100x over previous
#include <cuda_runtime.h>
#include <cuda_bf16.h>
#include <cstdint>

typedef unsigned long long u64;
typedef unsigned int u32;

// Shapes (fixed by the problem)
#define BB    8
#define CC    512
#define NN    1024
#define HH    8
#define DD    64
#define CQKV  1536

// LIF time-chunking: 8 chunks of 128 steps, 64-step warmup (v-decay 2^-64)
#define LCH   128
#define LWM   64

// ---------------------------------------------------------------------------
// Device scratch (allocation-free per harness rules)
// ---------------------------------------------------------------------------
__device__ __nv_bfloat16 g_xq[BB * CC * NN];         // pre-LIF spikes (bf16 0/1)
__device__ float g_z [BB * CQKV * NN];               // Wqkv @ xq (pre-BN, fp32)
__device__ __nv_bfloat16 g_sqh[BB * CC * NN];        // q spikes bf16
__device__ u64 g_kb[BB * CC * 16];                   // k spikes bitpacked along n
__device__ u64 g_vb[BB * CC * 16];                   // v spikes bitpacked along n
__device__ float g_y [BB * CC * NN];                 // attention out * 0.25
__device__ __nv_bfloat16 g_sy[BB * CC * NN];         // attn LIF spikes (bf16 0/1)
__device__ __nv_bfloat16 g_wA[3 * CQKV * CC];        // [3][1536][512] qkv splits
__device__ __nv_bfloat16 g_wP[3 * CC * CC];          // [3][512][512]  proj splits

// ---------------------------------------------------------------------------
// PTX helpers
// ---------------------------------------------------------------------------
__device__ __forceinline__ void cpa16(u32 dst, const void* src) {
    asm volatile("cp.async.cg.shared.global [%0], [%1], 16;\n" :: "r"(dst), "l"(src));
}
__device__ __forceinline__ void cpa_commit() {
    asm volatile("cp.async.commit_group;\n");
}
__device__ __forceinline__ void ldsm4(u32* r, u32 addr) {
    asm volatile("ldmatrix.sync.aligned.m8n8.x4.shared.b16 {%0,%1,%2,%3}, [%4];"
        : "=r"(r[0]), "=r"(r[1]), "=r"(r[2]), "=r"(r[3]) : "r"(addr));
}
__device__ __forceinline__ void ldsm4t(u32* r, u32 addr) {
    asm volatile("ldmatrix.sync.aligned.m8n8.x4.trans.shared.b16 {%0,%1,%2,%3}, [%4];"
        : "=r"(r[0]), "=r"(r[1]), "=r"(r[2]), "=r"(r[3]) : "r"(addr));
}
__device__ __forceinline__ void mma_bf16(float* d, const u32* a, u32 b0, u32 b1) {
    asm volatile(
        "mma.sync.aligned.m16n8k16.row.col.f32.bf16.bf16.f32 "
        "{%0,%1,%2,%3}, {%4,%5,%6,%7}, {%8,%9}, {%0,%1,%2,%3};"
        : "+f"(d[0]), "+f"(d[1]), "+f"(d[2]), "+f"(d[3])
        : "r"(a[0]), "r"(a[1]), "r"(a[2]), "r"(a[3]), "r"(b0), "r"(b1));
}

// ---------------------------------------------------------------------------
// Prep: 3-way bf16 split of weights, layout [split][m][k].
// ---------------------------------------------------------------------------
__global__ __launch_bounds__(256) void split_kernel(
    const float* __restrict__ wq, const float* __restrict__ wk,
    const float* __restrict__ wv, const float* __restrict__ wp)
{
    int idx = blockIdx.x * 256 + threadIdx.x;
    int m = idx >> 9, k = idx & 511;
    const float* src = (m < 512) ? wq : (m < 1024) ? wk : wv;
    float w = src[(size_t)(m & 511) * 512 + k];
    __nv_bfloat16 h1 = __float2bfloat16(w);
    float r1 = w - __bfloat162float(h1);
    __nv_bfloat16 h2 = __float2bfloat16(r1);
    float r2 = r1 - __bfloat162float(h2);
    __nv_bfloat16 h3 = __float2bfloat16(r2);
    g_wA[(size_t)m * 512 + k]              = h1;
    g_wA[(size_t)(CQKV + m) * 512 + k]     = h2;
    g_wA[(size_t)(2 * CQKV + m) * 512 + k] = h3;
    if (m < 512) {
        float w2 = wp[(size_t)m * 512 + k];
        __nv_bfloat16 p1 = __float2bfloat16(w2);
        float s1 = w2 - __bfloat162float(p1);
        __nv_bfloat16 p2 = __float2bfloat16(s1);
        float s2 = s1 - __bfloat162float(p2);
        __nv_bfloat16 p3 = __float2bfloat16(s2);
        g_wP[(size_t)m * 512 + k]            = p1;
        g_wP[(size_t)(CC + m) * 512 + k]     = p2;
        g_wP[(size_t)(2 * CC + m) * 512 + k] = p3;
    }
}

// ---------------------------------------------------------------------------
// GEMM (unchanged numerics): C[b][M][1024] = sum_s A_s[M][512] @ spikes.
// ---------------------------------------------------------------------------
#define ASTG (128 * 80)
#define A3SZ (3 * ASTG)
#define BSTG (32 * 256)
#define STGB (A3SZ + BSTG)
#define GSMEM (3 * STGB)

template<bool EPI>
__global__ __launch_bounds__(256) void gemm3_kernel(
    const __nv_bfloat16* __restrict__ W,
    const __nv_bfloat16* __restrict__ Bsp,
    float* __restrict__ C, int M,
    const float* __restrict__ bias, const float* __restrict__ bnp)
{
    extern __shared__ __align__(16) char smem[];
    const u32 smemBase = (u32)__cvta_generic_to_shared(smem);

    const int b  = blockIdx.z;
    const int mt = blockIdx.y;
    const int nt = blockIdx.x;
    const int tid  = threadIdx.x;
    const int lane = tid & 31;
    const int warp = tid >> 5;
    const int wm = warp & 3;
    const int wn = warp >> 2;

    const __nv_bfloat16* Bg = Bsp + (size_t)b * (512 * 1024) + nt * 128;

    float acc[2][8][4];
    #pragma unroll
    for (int i = 0; i < 2; i++)
        #pragma unroll
        for (int j = 0; j < 8; j++)
            #pragma unroll
            for (int r = 0; r < 4; r++) acc[i][j][r] = 0.0f;

    auto load_stage = [&](int st, int k0) {
        u32 sb = smemBase + st * STGB;
        #pragma unroll
        for (int s = 0; s < 3; s++) {
            #pragma unroll
            for (int j = 0; j < 2; j++) {
                int idx = tid * 2 + j;
                int ar = idx >> 2, ac = idx & 3;
                cpa16(sb + s * ASTG + ar * 80 + ac * 16,
                      W + ((size_t)(s * M + mt * 128 + ar)) * 512 + k0 + ac * 8);
            }
        }
        #pragma unroll
        for (int j = 0; j < 2; j++) {
            int idx = tid + j * 256;
            int br = idx >> 4, bc = idx & 15;
            cpa16(sb + A3SZ + br * 256 + ((bc ^ (br & 7)) << 4),
                  Bg + (size_t)(k0 + br) * 1024 + bc * 8);
        }
        cpa_commit();
    };

    load_stage(0, 0);
    load_stage(1, 32);

    for (int kt = 0; kt < 16; kt++) {
        if (kt + 2 < 16) load_stage((kt + 2) % 3, (kt + 2) * 32);
        else             cpa_commit();
        asm volatile("cp.async.wait_group 2;\n");
        __syncthreads();

        const u32 aB = smemBase + (kt % 3) * STGB;
        const u32 bB = aB + A3SZ;

        #pragma unroll
        for (int k16 = 0; k16 < 2; k16++) {
            u32 bfr[4][4];
            #pragma unroll
            for (int ni = 0; ni < 4; ni++) {
                int row = k16 * 16 + (lane & 15);
                int col = wn * 64 + ni * 16 + ((lane >> 4) << 3);
                int c = col >> 3;
                ldsm4t(bfr[ni], bB + row * 256 + ((c ^ (row & 7)) << 4));
            }
            #pragma unroll
            for (int s = 0; s < 3; s++) {
                u32 afr[2][4];
                #pragma unroll
                for (int mi = 0; mi < 2; mi++) {
                    int row = wm * 32 + mi * 16 + (lane & 15);
                    ldsm4(afr[mi], aB + s * ASTG + row * 80 + k16 * 32
                                   + ((lane >> 4) << 4));
                }
                #pragma unroll
                for (int mi = 0; mi < 2; mi++)
                    #pragma unroll
                    for (int j = 0; j < 8; j++)
                        mma_bf16(acc[mi][j], afr[mi],
                                 bfr[j >> 1][(j & 1) * 2],
                                 bfr[j >> 1][(j & 1) * 2 + 1]);
            }
        }
        __syncthreads();
    }

    #pragma unroll
    for (int mi = 0; mi < 2; mi++) {
        #pragma unroll
        for (int r = 0; r < 2; r++) {
            int grow = mt * 128 + wm * 32 + mi * 16 + (lane >> 2) + r * 8;
            float* crow = C + (size_t)b * M * 1024 + (size_t)grow * 1024
                          + nt * 128 + wn * 64 + (lane & 3) * 2;
            float inv = 1.0f, mu = 0.0f, be = 0.0f, bi = 0.0f;
            if (EPI) {
                float g  = bnp[grow];
                be = bnp[512 + grow];
                mu = bnp[1024 + grow];
                float va = bnp[1536 + grow];
                inv = g * rsqrtf(va + 1e-5f);
                bi = bias[grow];
            }
            #pragma unroll
            for (int j = 0; j < 8; j++) {
                float v0 = acc[mi][j][r * 2];
                float v1 = acc[mi][j][r * 2 + 1];
                if (EPI) {
                    v0 = (v0 + bi - mu) * inv + be;
                    v1 = (v1 + bi - mu) * inv + be;
                }
                *(float2*)(crow + j * 8) = make_float2(v0, v1);
            }
        }
    }
}

// ---------------------------------------------------------------------------
// LIF v3 (K1/K5): time-chunked. grid = (rowgroups, 8 chunks), 1 warp/block.
// Chunk c emits steps [c*128, (c+1)*128) after a 64-step warmup from v=0
// (except chunk 0). v-decay 0.5^64 makes emitted spikes match serial scan.
// ---------------------------------------------------------------------------
__global__ __launch_bounds__(32) void lif3_kernel(
    const float* __restrict__ in, const float* __restrict__ bnp,
    __nv_bfloat16* __restrict__ out, float vth)
{
    __shared__ float buf[32][33];
    const int lane = threadIdx.x;
    const int r0   = blockIdx.x * 32;
    const int row  = r0 + lane;
    const int ch   = blockIdx.y;

    float inv = 1.0f, mu = 0.0f, be = 0.0f;
    if (bnp) {
        int c = row & (CC - 1);
        inv = bnp[c] * (1.0f / sqrtf(bnp[3 * CC + c] + 1e-5f));
        be  = bnp[CC + c];
        mu  = bnp[2 * CC + c];
    }

    const int wt     = (ch == 0) ? 0 : (LWM / 32);   // warmup tiles
    const int ntiles = (LCH / 32) + wt;              // 4 or 6
    const int start  = ch * LCH - wt * 32;

    const float* src = in + (size_t)r0 * NN;
    __nv_bfloat16* dst = out + (size_t)row * NN;

    float4 nxt[8];
    #pragma unroll
    for (int i = 0; i < 8; i++) {
        int f = lane + 32 * i;
        nxt[i] = *(const float4*)(src + (size_t)(f >> 3) * NN + start + (f & 7) * 4);
    }

    float v = 0.0f;
    for (int t = 0; t < ntiles; t++) {
        #pragma unroll
        for (int i = 0; i < 8; i++) {
            int f = lane + 32 * i;
            int r = f >> 3, c0 = (f & 7) * 4;
            buf[r][c0 + 0] = nxt[i].x;
            buf[r][c0 + 1] = nxt[i].y;
            buf[r][c0 + 2] = nxt[i].z;
            buf[r][c0 + 3] = nxt[i].w;
        }
        __syncwarp();
        if (t + 1 < ntiles) {
            #pragma unroll
            for (int i = 0; i < 8; i++) {
                int f = lane + 32 * i;
                nxt[i] = *(const float4*)(src + (size_t)(f >> 3) * NN
                                          + start + (t + 1) * 32 + (f & 7) * 4);
            }
        }
        u32 pk[16];
        #pragma unroll
        for (int kk = 0; kk < 32; kk++) {
            float x  = buf[lane][kk];
            float xb = (x - mu) * inv + be;
            v = v + (xb - v) * 0.5f;
            bool sp = (v >= vth);
            v = sp ? 0.0f : v;
            u32 sb = sp ? 0x3F80u : 0u;
            if (kk & 1) pk[kk >> 1] |= sb << 16;
            else        pk[kk >> 1]  = sb;
        }
        __syncwarp();
        if (t >= wt) {
            int col = start + t * 32;
            #pragma unroll
            for (int j = 0; j < 4; j++) {
                uint4 q = make_uint4(pk[j*4], pk[j*4+1], pk[j*4+2], pk[j*4+3]);
                *(uint4*)(dst + col + j * 8) = q;
            }
        }
    }
}

// ---------------------------------------------------------------------------
// LIF v3 (K3): time-chunked BN+LIF on QKV output; q -> bf16, k/v -> bitpacked.
// Emit window is 128 steps = 2 u64 words -> clean bitpack per chunk.
// ---------------------------------------------------------------------------
__global__ __launch_bounds__(32) void lif_qkv3_kernel(
    const float* __restrict__ bnq, const float* __restrict__ bnk,
    const float* __restrict__ bnv)
{
    __shared__ float buf[32][33];
    const int lane = threadIdx.x;
    const int r0g  = blockIdx.x * 32;
    const int ch   = blockIdx.y;
    const int b    = r0g / CQKV;
    const int o    = r0g % CQKV;
    const int br   = o >> 9;
    const int c    = (o & 511) + lane;

    const float* bnp = (br == 0) ? bnq : (br == 1) ? bnk : bnv;
    float inv = bnp[c] * (1.0f / sqrtf(bnp[3 * CC + c] + 1e-5f));
    float be  = bnp[CC + c];
    float mu  = bnp[2 * CC + c];

    const int wt     = (ch == 0) ? 0 : (LWM / 32);
    const int ntiles = (LCH / 32) + wt;
    const int start  = ch * LCH - wt * 32;

    const float* src = g_z + (size_t)r0g * NN;
    __nv_bfloat16* qdst = g_sqh + ((size_t)b * CC + c) * NN;
    u64* bdst = ((br == 1) ? g_kb : g_vb) + ((size_t)b * CC + c) * 16;

    float4 nxt[8];
    #pragma unroll
    for (int i = 0; i < 8; i++) {
        int f = lane + 32 * i;
        nxt[i] = *(const float4*)(src + (size_t)(f >> 3) * NN + start + (f & 7) * 4);
    }

    float v = 0.0f;
    u32 prevbits = 0;
    for (int t = 0; t < ntiles; t++) {
        #pragma unroll
        for (int i = 0; i < 8; i++) {
            int f = lane + 32 * i;
            int r = f >> 3, c0 = (f & 7) * 4;
            buf[r][c0 + 0] = nxt[i].x;
            buf[r][c0 + 1] = nxt[i].y;
            buf[r][c0 + 2] = nxt[i].z;
            buf[r][c0 + 3] = nxt[i].w;
        }
        __syncwarp();
        if (t + 1 < ntiles) {
            #pragma unroll
            for (int i = 0; i < 8; i++) {
                int f = lane + 32 * i;
                nxt[i] = *(const float4*)(src + (size_t)(f >> 3) * NN
                                          + start + (t + 1) * 32 + (f & 7) * 4);
            }
        }
        u32 pk[16];
        u32 tb = 0;
        #pragma unroll
        for (int kk = 0; kk < 32; kk++) {
            float x  = buf[lane][kk];
            float xb = (x - mu) * inv + be;
            v = v + (xb - v) * 0.5f;
            bool sp = (v >= 1.0f);
            v = sp ? 0.0f : v;
            if (br == 0) {
                u32 sb = sp ? 0x3F80u : 0u;
                if (kk & 1) pk[kk >> 1] |= sb << 16;
                else        pk[kk >> 1]  = sb;
            } else {
                tb |= (sp ? 1u : 0u) << kk;
            }
        }
        __syncwarp();
        if (t >= wt) {
            int et  = t - wt;                 // emit tile 0..3
            int col = ch * LCH + et * 32;
            if (br == 0) {
                #pragma unroll
                for (int j = 0; j < 4; j++) {
                    uint4 q = make_uint4(pk[j*4], pk[j*4+1], pk[j*4+2], pk[j*4+3]);
                    *(uint4*)(qdst + col + j * 8) = q;
                }
            } else {
                if (et & 1) bdst[ch * 2 + (et >> 1)] = ((u64)tb << 32) | (u64)prevbits;
                else        prevbits = tb;
            }
        }
    }
}

// ---------------------------------------------------------------------------
// attn v3: y = q @ (k^T v) * 0.25 per (b,h); d-split x2, n-split x8.
// 128 threads/block, grid (8, 16, 8) = 1024 blocks.
// ---------------------------------------------------------------------------
__global__ __launch_bounds__(128) void attn3_kernel()
{
    __shared__ u64 kbs[64][16];
    __shared__ u64 vbs[32][16];
    __shared__ __align__(16) float Gs[64][32];

    const int nc = blockIdx.x;
    const int h  = blockIdx.y >> 1;
    const int dh = blockIdx.y & 1;
    const int b  = blockIdx.z;
    const int tid = threadIdx.x;
    const size_t base_c = (size_t)b * CC + h * DD;

    for (int i = tid; i < 64 * 16; i += 128) {
        int d = i >> 4, j = i & 15;
        kbs[d][j] = g_kb[(base_c + d) * 16 + j];
    }
    for (int i = tid; i < 32 * 16; i += 128) {
        int d = i >> 4, j = i & 15;
        vbs[d][j] = g_vb[(base_c + dh * 32 + d) * 16 + j];
    }
    __syncthreads();

    for (int e = tid; e < 64 * 32; e += 128) {
        int dp = e >> 5, dd = e & 31;
        int gsum = 0;
        #pragma unroll
        for (int j = 0; j < 16; j++)
            gsum += __popcll(kbs[dp][j] & vbs[dd][j]);
        Gs[dp][dd] = (float)gsum;
    }
    __syncthreads();

    const int n = nc * 128 + tid;
    const __nv_bfloat16* qb = g_sqh + base_c * NN + n;

    float acc[32];
    #pragma unroll
    for (int d = 0; d < 32; d++) acc[d] = 0.0f;

    #pragma unroll 4
    for (int dp = 0; dp < 64; dp++) {
        float qv = __bfloat162float(qb[(size_t)dp * NN]);
        const float4* gr = (const float4*)&Gs[dp][0];
        #pragma unroll
        for (int j = 0; j < 8; j++) {
            float4 g4 = gr[j];
            acc[j * 4 + 0] += qv * g4.x;
            acc[j * 4 + 1] += qv * g4.y;
            acc[j * 4 + 2] += qv * g4.z;
            acc[j * 4 + 3] += qv * g4.w;
        }
    }
    #pragma unroll
    for (int d = 0; d < 32; d++)
        g_y[(base_c + dh * 32 + d) * NN + n] = acc[d] * 0.25f;
}

// ---------------------------------------------------------------------------
// Launch
// ---------------------------------------------------------------------------
extern "C" void kernel_launch(void* const* d_in, const int* in_sizes, int n_in,
                              void* d_out, int out_size)
{
    const float* x       = (const float*)d_in[0];
    const float* bn_pre  = (const float*)d_in[1];
    const float* w_q     = (const float*)d_in[2];
    const float* bn_q    = (const float*)d_in[3];
    const float* w_k     = (const float*)d_in[4];
    const float* bn_k    = (const float*)d_in[5];
    const float* w_v     = (const float*)d_in[6];
    const float* bn_v    = (const float*)d_in[7];
    const float* w_proj  = (const float*)d_in[8];
    const float* b_proj  = (const float*)d_in[9];
    const float* bn_proj = (const float*)d_in[10];
    float* out = (float*)d_out;

    __nv_bfloat16* xq_ptr; cudaGetSymbolAddress((void**)&xq_ptr, g_xq);
    __nv_bfloat16* sy_ptr; cudaGetSymbolAddress((void**)&sy_ptr, g_sy);
    __nv_bfloat16* wA_ptr; cudaGetSymbolAddress((void**)&wA_ptr, g_wA);
    __nv_bfloat16* wP_ptr; cudaGetSymbolAddress((void**)&wP_ptr, g_wP);
    float* z_ptr;  cudaGetSymbolAddress((void**)&z_ptr, g_z);
    float* y_ptr;  cudaGetSymbolAddress((void**)&y_ptr, g_y);

    cudaFuncSetAttribute(gemm3_kernel<false>,
                         cudaFuncAttributeMaxDynamicSharedMemorySize, GSMEM);
    cudaFuncSetAttribute(gemm3_kernel<true>,
                         cudaFuncAttributeMaxDynamicSharedMemorySize, GSMEM);

    // P0: 3-way bf16 weight splits, [s][m][k]
    split_kernel<<<(CQKV * CC) / 256, 256>>>(w_q, w_k, w_v, w_proj);

    // K1: pre BN + LIF -> xq spikes (bf16), time-chunked
    lif3_kernel<<<dim3((BB * CC) / 32, NN / LCH), 32>>>(x, bn_pre, xq_ptr, 1.0f);

    // K2: fused QKV GEMM (tensor cores, shared-B 3-split)
    gemm3_kernel<false><<<dim3(8, 12, 8), 256, GSMEM>>>(
        wA_ptr, xq_ptr, z_ptr, CQKV, nullptr, nullptr);

    // K3: per-branch BN + LIF (time-chunked); q -> bf16, k/v -> bitpacked
    lif_qkv3_kernel<<<dim3((BB * CQKV) / 32, NN / LCH), 32>>>(bn_q, bn_k, bn_v);

    // K4: linear attention via G = k^T v (popcount), y = q G * 0.25
    attn3_kernel<<<dim3(8, 16, 8), 128>>>();

    // K5: attn LIF (threshold 0.5, no BN) -> sy spikes (bf16), time-chunked
    lif3_kernel<<<dim3((BB * CC) / 32, NN / LCH), 32>>>(y_ptr, nullptr, sy_ptr, 0.5f);

    // K6: projection GEMM + bias + bn_proj fused epilogue -> out
    gemm3_kernel<true><<<dim3(8, 4, 8), 256, GSMEM>>>(
        wP_ptr, sy_ptr, out, CC, b_proj, bn_proj);
}